// round 3
// baseline (speedup 1.0000x reference)
#include <cuda_runtime.h>

// B-spline layer: out[b,f] = sum_{k} N_k(x[b,f]) * cp[k,f] + bias[f]
// Cubic clamped uniform B-spline, K=64 knots -> interior spacing h = 1/61.
// Only 4 basis functions are nonzero per x; span m = floor(61*x) in [0,60],
// nonzero control indices are m..m+3. Work in knot units (u = 61*x) so all
// knot values are small integers and h cancels; denominators are in {1,2,3}
// so 1/den is computed with FMAs (no MUFU RCP).

#define NK 64
#define NF 128

__global__ __launch_bounds__(512, 3)
void bspline_kernel(const float* __restrict__ x,
                    const float* __restrict__ cp,
                    const float* __restrict__ bias,
                    float* __restrict__ out,
                    int B)
{
    __shared__ float cs[NK * NF];   // 32 KB, control points [k][f]

    const int tid = threadIdx.x;

    // Cooperative fill of control points: 8192 floats = 2048 float4 / 512 thr = 4 each
    {
        const float4* __restrict__ src = (const float4*)cp;
        float4* dst = (float4*)cs;
#pragma unroll
        for (int i = 0; i < (NK * NF / 4) / 512; i++)
            dst[tid + i * 512] = src[tid + i * 512];
    }

    const int f    = tid & (NF - 1);   // fixed feature column per thread
    const int lrow = tid >> 7;         // 0..3 : local row within block-iteration
    const float bf = __ldg(&bias[f]);

    __syncthreads();

    const int rowStride = gridDim.x * 4;
    for (int row = blockIdx.x * 4 + lrow; row < B; row += rowStride) {
        const float xv = x[row * NF + f];

        // span in knot units
        float u  = xv * 61.0f;
        float fm = floorf(u);
        fm = fminf(fmaxf(fm, 0.0f), 60.0f);
        const int m = (int)fm;

        // clamped knot values (in units of h) around the span
        const float k1  = fm + 1.0f;                 // never clamps (<= 61)
        const float km1 = fmaxf(fm - 1.0f, 0.0f);
        const float km2 = fmaxf(fm - 2.0f, 0.0f);
        const float k2  = fminf(fm + 2.0f, 61.0f);
        const float k3  = fminf(fm + 3.0f, 61.0f);

        const float l1 = u - fm;
        const float r1 = k1 - u;
        const float l2 = u - km1;
        const float l3 = u - km2;
        const float r2 = k2 - u;
        const float r3 = k3 - u;

        // reciprocal denominators (integer-valued knot differences)
        const float n21 = k1 - km1;                              // {1,2}
        const float i21 = fmaf(n21, -0.5f, 1.5f);
        const float n22 = k2 - fm;                               // {1,2}
        const float i22 = fmaf(n22, -0.5f, 1.5f);
        const float n31 = k1 - km2;                              // {1,2,3}
        const float t31 = fmaf(n31, 0.16666667f, -1.0f);
        const float i31 = fmaf(n31, t31, 1.8333334f);
        const float n32 = k2 - km1;                              // {2,3}
        const float i32 = fmaf(n32, -0.16666667f, 0.8333333f);
        const float n33 = k3 - fm;                               // {1,2,3}
        const float t33 = fmaf(n33, 0.16666667f, -1.0f);
        const float i33 = fmaf(n33, t33, 1.8333334f);

        // Cox-de Boor, degree 1 -> 3 (N[r] = B_{m+r})
        float N0 = r1, N1 = l1;

        // degree 2
        float tmp = N0 * i21;
        N0 = r1 * tmp;
        float sv = l2 * tmp;
        tmp = N1 * i22;
        N1 = fmaf(r2, tmp, sv);
        float N2 = l1 * tmp;

        // degree 3
        tmp = N0 * i31;
        N0 = r1 * tmp;
        sv  = l3 * tmp;
        tmp = N1 * i32;
        N1 = fmaf(r2, tmp, sv);
        sv  = l2 * tmp;
        tmp = N2 * i33;
        N2 = fmaf(r3, tmp, sv);
        const float N3 = l1 * tmp;

        // 4-term dot with control rows m..m+3 (bank-conflict-free: bank = f%32 = lane)
        const float* __restrict__ c = &cs[m * NF + f];
        float acc = fmaf(N0, c[0 * NF], bf);
        acc = fmaf(N1, c[1 * NF], acc);
        acc = fmaf(N2, c[2 * NF], acc);
        acc = fmaf(N3, c[3 * NF], acc);

        out[row * NF + f] = acc;
    }
}

extern "C" void kernel_launch(void* const* d_in, const int* in_sizes, int n_in,
                              void* d_out, int out_size)
{
    const float* x    = (const float*)d_in[0];
    const float* cp   = (const float*)d_in[1];
    const float* bias = (const float*)d_in[2];
    float* out = (float*)d_out;

    const int B = in_sizes[0] / NF;   // 16384 rows

    // Persistent-style grid: ~3 blocks per SM (152 SMs on GB300) to keep the
    // 32KB smem control-point fill traffic low while saturating the chip.
    int grid = 456;
    int maxBlocks = (B + 3) / 4;
    if (grid > maxBlocks) grid = maxBlocks;

    bspline_kernel<<<grid, 512>>>(x, cp, bias, out, B);
}

// round 4
// speedup vs baseline: 1.0269x; 1.0269x over previous
#include <cuda_runtime.h>

// B-spline layer: out[b,f] = sum_k N_k(x[b,f]) * cp[k,f] + bias[f]
// Cubic clamped uniform B-spline, K=64 -> interior spacing h = 1/61.
// Only 4 basis funcs nonzero per x; span m = floor(61*x) in [0,60].
// Work in knot units so knots are small integers; 1/den for den in {1,2,3}
// via linear+clamp FMAs (exact at integer den) -- no MUFU RCP.
// ILP=4: each thread processes 4 rows per iteration to hide LDG/LDS latency.

#define NK 64
#define NF 128
#define U  4

__global__ __launch_bounds__(512)
void bspline_kernel(const float* __restrict__ x,
                    const float* __restrict__ cp,
                    const float* __restrict__ bias,
                    float* __restrict__ out,
                    int B)
{
    __shared__ float cs[NK * NF];   // 32 KB control points [k][f]

    const int tid = threadIdx.x;

    // Cooperative fill: 8192 floats = 2048 float4 / 512 thr = 4 each
    {
        const float4* __restrict__ src = (const float4*)cp;
        float4* dst = (float4*)cs;
#pragma unroll
        for (int i = 0; i < (NK * NF / 4) / 512; i++)
            dst[tid + i * 512] = src[tid + i * 512];
    }

    const int f    = tid & (NF - 1);   // feature column (bank = lane -> conflict-free)
    const int lrow = tid >> 7;         // 0..3
    const float bf = __ldg(&bias[f]);

    __syncthreads();

    const int rowStride = gridDim.x * (4 * U);          // 16 rows per block-iter
    for (int base = blockIdx.x * (4 * U) + lrow * U; base < B; base += rowStride) {
        // Batch the 4 global loads up front (MLP = 4)
        float xv[U];
#pragma unroll
        for (int j = 0; j < U; j++)
            xv[j] = x[(base + j) * NF + f];

        float acc[U];
#pragma unroll
        for (int j = 0; j < U; j++) {
            const float u  = xv[j] * 61.0f;
            const float fm = floorf(u);          // x in [0,1) -> m in [0,60], no clamp
            const int   m  = (int)fm;

            const float km1 = fmaxf(fm - 1.0f, 0.0f);
            const float km2 = fmaxf(fm - 2.0f, 0.0f);
            const float k2  = fminf(fm + 2.0f, 61.0f);
            const float k3  = fminf(fm + 3.0f, 61.0f);

            const float l1 = u - fm;
            const float r1 = fm + 1.0f - u;
            const float l2 = u - km1;
            const float l3 = u - km2;
            const float r2 = k2 - u;
            const float r3 = k3 - u;

            // reciprocal denominators: linear + clamp, exact at integer knot gaps
            const float lo = fmaf(fm, -0.5f,   1.0f);   // shared by i21/i31
            const float hi = fmaf(fm,  0.5f, -29.0f);   // shared by i22/i33
            const float i21 = fmaxf(0.5f,        lo);   // m=0:1,  m>=1: 1/2
            const float i22 = fmaxf(0.5f,        hi);   // m=60:1, m<=59: 1/2
            const float i31 = fmaxf(0.33333334f, lo);   // m=0:1, m=1:1/2, else 1/3
            const float i33 = fmaxf(0.33333334f, hi);   // m=60:1, 59:1/2, else 1/3
            const float i32 = fmaf(k2 - km1, -0.16666667f, 0.83333331f); // 1/{2,3}

            // Cox-de Boor degree 1 -> 2
            float t  = r1 * i21;
            float N0 = r1 * t;
            float s  = l2 * t;
            t        = l1 * i22;
            float N1 = fmaf(r2, t, s);
            float N2 = l1 * t;

            // degree 2 -> 3
            t  = N0 * i31;
            N0 = r1 * t;
            s  = l3 * t;
            t  = N1 * i32;
            N1 = fmaf(r2, t, s);
            s  = l2 * t;
            t  = N2 * i33;
            N2 = fmaf(r3, t, s);
            const float N3 = l1 * t;

            // 4-term dot with control rows m..m+3 (conflict-free smem gather)
            const float* __restrict__ c = &cs[m * NF + f];
            float a = fmaf(N0, c[0 * NF], bf);
            a = fmaf(N1, c[1 * NF], a);
            a = fmaf(N2, c[2 * NF], a);
            a = fmaf(N3, c[3 * NF], a);
            acc[j] = a;
        }

#pragma unroll
        for (int j = 0; j < U; j++)
            out[(base + j) * NF + f] = acc[j];
    }
}

extern "C" void kernel_launch(void* const* d_in, const int* in_sizes, int n_in,
                              void* d_out, int out_size)
{
    const float* x    = (const float*)d_in[0];
    const float* cp   = (const float*)d_in[1];
    const float* bias = (const float*)d_in[2];
    float* out = (float*)d_out;

    const int B = in_sizes[0] / NF;   // 16384 rows

    // grid 512 * 16 rows/iter = 8192 rows/sweep -> exactly 2 uniform iterations
    int grid = (B + (4 * U) - 1) / (4 * U);
    if (grid > 512) grid = 512;

    bspline_kernel<<<grid, 512>>>(x, cp, bias, out, B);
}